// round 9
// baseline (speedup 1.0000x reference)
#include <cuda_runtime.h>
#include <cuda_fp16.h>
#include <stdint.h>

#define T 1024
#define Hd 1024
#define Id 1024
#define NE 16
#define TOPK 4

// ---------------- scratch (no runtime allocation allowed) ----------------
__device__ __align__(16) __half g_xn[T * Hd];             // normed activations, fp16
__device__ int   g_cnt[NE];
__device__ int   g_perm[NE * T];
__device__ float g_gate[NE * T];
__device__ __align__(16) __half g_s[(size_t)NE * T * Id]; // swiglu output, fp16

// ---------------- shared memory map ----------------
// As  : 4 stages x [128][40] half   = 40960 B   (reused as epilogue staging)
// B16 : 2 bufs   x [32][136] half   = 17408 B
// meta: tok/gate                    = 1024 B
#define OFF_A    0
#define OFF_B16  40960
#define OFF_TOK  (40960 + 17408)            // 58368
#define OFF_GATE (58368 + 512)
#define DYN_SMEM (58368 + 1024)             // 59392

// ---------------- kernel 0: count reset ----------------
__global__ void k_zero() { if (threadIdx.x < NE) g_cnt[threadIdx.x] = 0; }

// ---------------- kernel 1: RMSNorm + router + residual copy ----------------
__global__ __launch_bounds__(256) void k_norm_route(
    const float* __restrict__ x, const float* __restrict__ ns,
    const float* __restrict__ wg, const float* __restrict__ bg,
    float* __restrict__ out)
{
    int t = blockIdx.x;
    int tid = threadIdx.x;
    int lane = tid & 31, warp = tid >> 5;

    const float4 xv = ((const float4*)(x + (size_t)t * Hd))[tid];
    ((float4*)(out + (size_t)t * Hd))[tid] = xv;          // residual init
    float ss = xv.x * xv.x + xv.y * xv.y + xv.z * xv.z + xv.w * xv.w;
    #pragma unroll
    for (int o = 16; o; o >>= 1) ss += __shfl_xor_sync(0xffffffffu, ss, o);

    __shared__ float sred[8];
    __shared__ float slog[8][16];
    __shared__ float logits[16];
    if (lane == 0) sred[warp] = ss;
    __syncthreads();
    float tot = sred[0] + sred[1] + sred[2] + sred[3] + sred[4] + sred[5] + sred[6] + sred[7];
    float rms = rsqrtf(tot * (1.0f / Hd) + 1e-5f);

    int h0 = tid * 4;
    float xn0 = xv.x * rms * ns[h0 + 0];
    float xn1 = xv.y * rms * ns[h0 + 1];
    float xn2 = xv.z * rms * ns[h0 + 2];
    float xn3 = xv.w * rms * ns[h0 + 3];

    __half2* dst = (__half2*)(g_xn + (size_t)t * Hd + h0);
    dst[0] = __floats2half2_rn(xn0, xn1);
    dst[1] = __floats2half2_rn(xn2, xn3);

    const float* w0 = wg + (size_t)h0 * NE;
    float acc[NE];
    #pragma unroll
    for (int e = 0; e < NE; e++)
        acc[e] = xn0 * w0[e] + xn1 * w0[NE + e] + xn2 * w0[2 * NE + e] + xn3 * w0[3 * NE + e];
    #pragma unroll
    for (int e = 0; e < NE; e++)
        #pragma unroll
        for (int o = 16; o; o >>= 1) acc[e] += __shfl_xor_sync(0xffffffffu, acc[e], o);
    if (lane == 0) {
        #pragma unroll
        for (int e = 0; e < NE; e++) slog[warp][e] = acc[e];
    }
    __syncthreads();
    if (tid < NE) {
        float s = bg[tid];
        #pragma unroll
        for (int w = 0; w < 8; w++) s += slog[w][tid];
        logits[tid] = s;
    }
    __syncthreads();
    if (tid == 0) {
        float vals[TOPK]; int idx[TOPK];
        unsigned used = 0;
        for (int k = 0; k < TOPK; k++) {
            float best = -1e30f; int bi = 0;
            for (int e = 0; e < NE; e++)
                if (!((used >> e) & 1u) && logits[e] > best) { best = logits[e]; bi = e; }
            used |= 1u << bi; vals[k] = best; idx[k] = bi;
        }
        float ex[TOPK], den = 0.f;
        for (int k = 0; k < TOPK; k++) { ex[k] = __expf(vals[k] - vals[0]); den += ex[k]; }
        float inv = 1.f / den;
        for (int k = 0; k < TOPK; k++) {
            int e = idx[k];
            int pos = atomicAdd(&g_cnt[e], 1);
            g_perm[e * T + pos] = t;
            g_gate[e * T + pos] = ex[k] * inv;
        }
    }
}

// ---------------- helpers ----------------
__device__ __forceinline__ void mma16816(float* c, const uint32_t* a, const uint32_t* b) {
    asm volatile(
        "mma.sync.aligned.m16n8k16.row.col.f32.f16.f16.f32 "
        "{%0,%1,%2,%3}, {%4,%5,%6,%7}, {%8,%9}, {%0,%1,%2,%3};\n"
        : "+f"(c[0]), "+f"(c[1]), "+f"(c[2]), "+f"(c[3])
        : "r"(a[0]), "r"(a[1]), "r"(a[2]), "r"(a[3]), "r"(b[0]), "r"(b[1]));
}
__device__ __forceinline__ void cpa16(void* dst, const void* src, int sz) {
    uint32_t d = (uint32_t)__cvta_generic_to_shared(dst);
    asm volatile("cp.async.cg.shared.global [%0], [%1], 16, %2;\n" :: "r"(d), "l"(src), "r"(sz));
}
__device__ __forceinline__ void cpa_commit() { asm volatile("cp.async.commit_group;\n"); }
__device__ __forceinline__ void cpa_wait2()  { asm volatile("cp.async.wait_group 2;\n"); }
__device__ __forceinline__ uint32_t h2pack(float a, float b) {
    __half2 h = __floats2half2_rn(a, b);
    return *(uint32_t*)&h;
}
__device__ __forceinline__ void ldsm4(uint32_t* r, const void* p) {
    uint32_t addr = (uint32_t)__cvta_generic_to_shared(p);
    asm volatile("ldmatrix.sync.aligned.m8n8.x4.shared.b16 {%0,%1,%2,%3}, [%4];"
        : "=r"(r[0]), "=r"(r[1]), "=r"(r[2]), "=r"(r[3]) : "r"(addr));
}
__device__ __forceinline__ void ldsm4t(uint32_t* r, const void* p) {
    uint32_t addr = (uint32_t)__cvta_generic_to_shared(p);
    asm volatile("ldmatrix.sync.aligned.m8n8.x4.trans.shared.b16 {%0,%1,%2,%3}, [%4];"
        : "=r"(r[0]), "=r"(r[1]), "=r"(r[2]), "=r"(r[3]) : "r"(addr));
}

// smem views: As[4][128][40] half, B16[2][32][136] half
struct SmemView {
    __half (*As)[128][40];
    __half (*B16)[32][136];
    int* rowTok;
    float* rowGate;
};
__device__ __forceinline__ SmemView smview(char* base) {
    SmemView s;
    s.As     = (__half(*)[128][40])(base + OFF_A);
    s.B16    = (__half(*)[32][136])(base + OFF_B16);
    s.rowTok = (int*)(base + OFF_TOK);
    s.rowGate= (float*)(base + OFF_GATE);
    return s;
}

// B register-path: thread (ck = tid>>3, l = tid&7) owns row ck, cols {l*4 + j*32}
__device__ __forceinline__ void ldgB(float4* rF, const float* __restrict__ w,
                                     int ld, int k0, int nBase, int tid) {
    int ck = tid >> 3, l = tid & 7;
    const float* row = w + (size_t)(k0 + ck) * ld + nBase + l * 4;
    #pragma unroll
    for (int j = 0; j < 4; j++) rF[j] = *(const float4*)(row + j * 32);
}
__device__ __forceinline__ void stsB(SmemView& sv, int buf, const float4* rF, int tid) {
    int ck = tid >> 3, l = tid & 7;
    #pragma unroll
    for (int j = 0; j < 4; j++) {
        uint2 p = make_uint2(h2pack(rF[j].x, rF[j].y), h2pack(rF[j].z, rF[j].w));
        *(uint2*)&sv.B16[buf][ck][l * 4 + j * 32] = p;
    }
}

// ---------------- kernel 2: grouped GEMM1 + swiglu (n-split halves) ----------
// grid (nTile=8, mTile=4, expert=16), block 256 (8 warps 2x4); nOff selects half
__global__ __launch_bounds__(256, 2) void k_ffn1(
    const float* __restrict__ w1, const float* __restrict__ b1, int nOff)
{
    extern __shared__ char smbase[];
    SmemView sv = smview(smbase);

    int e = blockIdx.z;
    int cnt = g_cnt[e];
    int mBase = blockIdx.y * 128;
    if (mBase >= cnt) return;
    int nBase = (blockIdx.x + nOff) * 128;
    int validRows = cnt - mBase; if (validRows > 128) validRows = 128;

    int tid = threadIdx.x;
    if (tid < 128) {
        int slot = mBase + tid;
        sv.rowTok[tid] = (slot < cnt) ? g_perm[e * T + slot] : -1;
    }
    __syncthreads();

    int lane = tid & 31, warp = tid >> 5;
    int wm = warp >> 2, wn = warp & 3;
    bool warpLive = (wm * 64) < validRows;

    float acc[4][4][4];
    #pragma unroll
    for (int mf = 0; mf < 4; mf++)
        #pragma unroll
        for (int nf = 0; nf < 4; nf++)
            #pragma unroll
            for (int i = 0; i < 4; i++) acc[mf][nf][i] = 0.f;

    auto issueA = [&](int s) {
        int k0 = s * 32;
        #pragma unroll
        for (int c = 0; c < 2; c++) {
            int ch = tid + c * 256;
            int row = ch >> 2, col = (ch & 3) * 8;
            int tok = sv.rowTok[row];
            if (tok >= 0) cpa16(&sv.As[s & 3][row][col], g_xn + (size_t)tok * Hd + k0 + col, 16);
            else          cpa16(&sv.As[s & 3][row][col], g_xn, 0);
        }
    };

    const int LD = 2 * Id;
    float4 rF[4];

    issueA(0); cpa_commit();
    issueA(1); cpa_commit();
    issueA(2); cpa_commit();
    ldgB(rF, w1 + (size_t)e * Hd * LD, LD, 0, nBase, tid);
    stsB(sv, 0, rF, tid);
    ldgB(rF, w1 + (size_t)e * Hd * LD, LD, 32, nBase, tid);

    const int KT = Hd / 32;
    for (int it = 0; it < KT; it++) {
        cpa_wait2();
        __syncthreads();
        if (it + 1 < KT) stsB(sv, (it + 1) & 1, rF, tid);
        if (warpLive) {
            #pragma unroll
            for (int kk = 0; kk < 32; kk += 16) {
                uint32_t a[4][4], b[4][2];
                #pragma unroll
                for (int mf = 0; mf < 4; mf++) {
                    int r = wm * 64 + mf * 16 + (lane & 15);
                    ldsm4(a[mf], &sv.As[it & 3][r][kk + (lane >> 4) * 8]);
                }
                #pragma unroll
                for (int pair = 0; pair < 2; pair++) {
                    int m = lane >> 3, r = lane & 7;
                    uint32_t rr[4];
                    ldsm4t(rr, &sv.B16[it & 1][kk + (m & 1) * 8 + r][wn * 32 + pair * 16 + (m >> 1) * 8]);
                    b[pair * 2 + 0][0] = rr[0]; b[pair * 2 + 0][1] = rr[1];
                    b[pair * 2 + 1][0] = rr[2]; b[pair * 2 + 1][1] = rr[3];
                }
                #pragma unroll
                for (int mf = 0; mf < 4; mf++)
                    #pragma unroll
                    for (int nf = 0; nf < 4; nf++)
                        mma16816(acc[mf][nf], a[mf], b[nf]);
            }
        }
        if (it + 2 < KT) ldgB(rF, w1 + (size_t)e * Hd * LD, LD, (it + 2) * 32, nBase, tid);
        if (it + 3 < KT) issueA(it + 3);
        cpa_commit();
    }

    // ---- epilogue: swiglu -> smem staging (reuse As area) -> coalesced g_s ----
    __half (*Ss)[72] = (__half(*)[72])(smbase + OFF_A);  // 128 x 72 half = 18432 B
    __syncthreads();                                      // all done reading As/B16
    if (warpLive) {
        int g = lane >> 2, tg = lane & 3;
        #pragma unroll
        for (int mf = 0; mf < 4; mf++) {
            #pragma unroll
            for (int nf = 0; nf < 4; nf++) {
                int ncol = nBase + wn * 32 + nf * 8 + tg * 2;   // even
                float ba = b1[e * (2 * Id) + ncol];
                float bb = b1[e * (2 * Id) + ncol + 1];
                int sl = wn * 16 + nf * 4 + tg;                 // local scol 0..63
                #pragma unroll
                for (int h = 0; h < 2; h++) {
                    int row = wm * 64 + mf * 16 + g + h * 8;
                    float av = acc[mf][nf][h * 2 + 0] + ba;
                    float bv = acc[mf][nf][h * 2 + 1] + bb;
                    av = fminf(av, 7.0f);
                    bv = fminf(fmaxf(bv, -7.0f), 7.0f);
                    float sig = __frcp_rn(1.f + __expf(-1.702f * av));
                    Ss[row][sl] = __float2half(av * sig * (bv + 1.f));
                }
            }
        }
    }
    __syncthreads();
    // copy: 32 rows per pass x 4 passes; 8 threads cover one 128B row
    {
        int r0 = tid >> 3, cl = (tid & 7) * 8;   // cl: half offset 0..56
        #pragma unroll
        for (int p = 0; p < 4; p++) {
            int row = p * 32 + r0;
            int slot = mBase + row;
            if (slot < cnt) {
                uint4 v = *(uint4*)&Ss[row][cl];
                *(uint4*)(g_s + ((size_t)(e * T + slot)) * Id + (nBase >> 1) + cl) = v;
            }
        }
    }
}

// ---------------- kernel 3: grouped GEMM2 + gated scatter ----------------
// grid (nTile=8, mTile=4, expert=16), block 256
__global__ __launch_bounds__(256, 2) void k_ffn2(
    const float* __restrict__ w2, const float* __restrict__ b2, float* __restrict__ out)
{
    extern __shared__ char smbase[];
    SmemView sv = smview(smbase);

    int e = blockIdx.z;
    int cnt = g_cnt[e];
    int mBase = blockIdx.y * 128;
    if (mBase >= cnt) return;
    int nBase = blockIdx.x * 128;
    int validRows = cnt - mBase; if (validRows > 128) validRows = 128;

    int tid = threadIdx.x;
    if (tid < 128) {
        int slot = mBase + tid;
        if (slot < cnt) { sv.rowTok[tid] = g_perm[e * T + slot]; sv.rowGate[tid] = g_gate[e * T + slot]; }
        else            { sv.rowTok[tid] = -1;                   sv.rowGate[tid] = 0.f; }
    }
    __syncthreads();

    int lane = tid & 31, warp = tid >> 5;
    int wm = warp >> 2, wn = warp & 3;
    bool warpLive = (wm * 64) < validRows;

    float acc[4][4][4];
    #pragma unroll
    for (int mf = 0; mf < 4; mf++)
        #pragma unroll
        for (int nf = 0; nf < 4; nf++)
            #pragma unroll
            for (int i = 0; i < 4; i++) acc[mf][nf][i] = 0.f;

    auto issueA = [&](int s) {
        int k0 = s * 32;
        #pragma unroll
        for (int c = 0; c < 2; c++) {
            int ch = tid + c * 256;
            int row = ch >> 2, col = (ch & 3) * 8;
            int valid = (row < validRows) ? 16 : 0;
            const __half* src = g_s + ((size_t)(e * T + mBase + row)) * Id + k0 + col;
            cpa16(&sv.As[s & 3][row][col], src, valid);
        }
    };

    float4 rF[4];

    issueA(0); cpa_commit();
    issueA(1); cpa_commit();
    issueA(2); cpa_commit();
    ldgB(rF, w2 + (size_t)e * Id * Hd, Hd, 0, nBase, tid);
    stsB(sv, 0, rF, tid);
    ldgB(rF, w2 + (size_t)e * Id * Hd, Hd, 32, nBase, tid);

    const int KT = Id / 32;
    for (int it = 0; it < KT; it++) {
        cpa_wait2();
        __syncthreads();
        if (it + 1 < KT) stsB(sv, (it + 1) & 1, rF, tid);
        if (warpLive) {
            #pragma unroll
            for (int kk = 0; kk < 32; kk += 16) {
                uint32_t a[4][4], b[4][2];
                #pragma unroll
                for (int mf = 0; mf < 4; mf++) {
                    int r = wm * 64 + mf * 16 + (lane & 15);
                    ldsm4(a[mf], &sv.As[it & 3][r][kk + (lane >> 4) * 8]);
                }
                #pragma unroll
                for (int pair = 0; pair < 2; pair++) {
                    int m = lane >> 3, r = lane & 7;
                    uint32_t rr[4];
                    ldsm4t(rr, &sv.B16[it & 1][kk + (m & 1) * 8 + r][wn * 32 + pair * 16 + (m >> 1) * 8]);
                    b[pair * 2 + 0][0] = rr[0]; b[pair * 2 + 0][1] = rr[1];
                    b[pair * 2 + 1][0] = rr[2]; b[pair * 2 + 1][1] = rr[3];
                }
                #pragma unroll
                for (int mf = 0; mf < 4; mf++)
                    #pragma unroll
                    for (int nf = 0; nf < 4; nf++)
                        mma16816(acc[mf][nf], a[mf], b[nf]);
            }
        }
        if (it + 2 < KT) ldgB(rF, w2 + (size_t)e * Id * Hd, Hd, (it + 2) * 32, nBase, tid);
        if (it + 3 < KT) issueA(it + 3);
        cpa_commit();
    }

    if (warpLive) {
        int g = lane >> 2, tg = lane & 3;
        #pragma unroll
        for (int mf = 0; mf < 4; mf++) {
            #pragma unroll
            for (int nf = 0; nf < 4; nf++) {
                int ncol = nBase + wn * 32 + nf * 8 + tg * 2;
                float b2a = b2[e * Hd + ncol];
                float b2b = b2[e * Hd + ncol + 1];
                #pragma unroll
                for (int h = 0; h < 2; h++) {
                    int row = wm * 64 + mf * 16 + g + h * 8;
                    int slot = mBase + row;
                    if (slot < cnt) {
                        int tok = sv.rowTok[row];
                        float gt = sv.rowGate[row];
                        atomicAdd(&out[(size_t)tok * Hd + ncol],     gt * (acc[mf][nf][h * 2 + 0] + b2a));
                        atomicAdd(&out[(size_t)tok * Hd + ncol + 1], gt * (acc[mf][nf][h * 2 + 1] + b2b));
                    }
                }
            }
        }
    }
}

// ---------------- launch ----------------
extern "C" void kernel_launch(void* const* d_in, const int* in_sizes, int n_in,
                              void* d_out, int out_size)
{
    const float* x  = (const float*)d_in[0];
    const float* ns = (const float*)d_in[1];
    const float* wg = (const float*)d_in[2];
    const float* bg = (const float*)d_in[3];
    const float* w1 = (const float*)d_in[4];
    const float* b1 = (const float*)d_in[5];
    const float* w2 = (const float*)d_in[6];
    const float* b2 = (const float*)d_in[7];
    float* out = (float*)d_out;

    cudaFuncSetAttribute(k_ffn1, cudaFuncAttributeMaxDynamicSharedMemorySize, DYN_SMEM);
    cudaFuncSetAttribute(k_ffn2, cudaFuncAttributeMaxDynamicSharedMemorySize, DYN_SMEM);

    k_zero<<<1, 32>>>();
    k_norm_route<<<1024, 256>>>(x, ns, wg, bg, out);
    k_ffn1<<<dim3(8, 4, 16), 256, DYN_SMEM>>>(w1, b1, 0);
    k_ffn1<<<dim3(8, 4, 16), 256, DYN_SMEM>>>(w1, b1, 8);
    k_ffn2<<<dim3(8, 4, 16), 256, DYN_SMEM>>>(w2, b2, out);
}

// round 11
// speedup vs baseline: 1.2984x; 1.2984x over previous
#include <cuda_runtime.h>
#include <cuda_fp16.h>
#include <stdint.h>

#define T 1024
#define Hd 1024
#define Id 1024
#define NE 16
#define TOPK 4

// ---------------- scratch (no runtime allocation allowed) ----------------
__device__ __align__(16) __half g_xn[T * Hd];             // normed activations, fp16
__device__ int   g_cnt[NE];
__device__ int   g_perm[NE * T];
__device__ float g_gate[NE * T];
__device__ __align__(16) __half g_s[(size_t)NE * T * Id]; // swiglu output, fp16

// ---------------- shared memory map ----------------
// As  : 4 stages x [128][40] half   = 40960 B   (reused as epilogue staging)
// B16 : 2 bufs   x [32][136] half   = 17408 B
// meta: tok/gate                    = 1024 B
#define OFF_A    0
#define OFF_B16  40960
#define OFF_TOK  (40960 + 17408)            // 58368
#define OFF_GATE (58368 + 512)
#define DYN_SMEM (58368 + 1024)             // 59392

// ---------------- kernel 0: count reset ----------------
__global__ void k_zero() { if (threadIdx.x < NE) g_cnt[threadIdx.x] = 0; }

// ---------------- kernel 1: RMSNorm + router + residual (warp-per-token) ----
// grid 128, block 256 (8 warps = 8 tokens per block)
// Each token row = 1024 floats = 256 float4; each lane handles 8 float4.
__global__ __launch_bounds__(256) void k_norm_route(
    const float* __restrict__ x, const float* __restrict__ ns,
    const float* __restrict__ wg, const float* __restrict__ bg,
    float* __restrict__ out)
{
    int warp = threadIdx.x >> 5, lane = threadIdx.x & 31;
    int t = blockIdx.x * 8 + warp;

    const float4* xr = (const float4*)(x + (size_t)t * Hd);
    float4 xv[8];
    #pragma unroll
    for (int j = 0; j < 8; j++) xv[j] = xr[j * 32 + lane];

    float ss = 0.f;
    #pragma unroll
    for (int j = 0; j < 8; j++)
        ss += xv[j].x * xv[j].x + xv[j].y * xv[j].y + xv[j].z * xv[j].z + xv[j].w * xv[j].w;
    #pragma unroll
    for (int o = 16; o; o >>= 1) ss += __shfl_xor_sync(0xffffffffu, ss, o);
    float rms = rsqrtf(ss * (1.0f / Hd) + 1e-5f);

    // residual copy (full row)
    float4* orow = (float4*)(out + (size_t)t * Hd);
    #pragma unroll
    for (int j = 0; j < 8; j++) orow[j * 32 + lane] = xv[j];

    // normalize, store fp16, accumulate router partials
    float acc[NE];
    #pragma unroll
    for (int e = 0; e < NE; e++) acc[e] = 0.f;

    #pragma unroll
    for (int j = 0; j < 8; j++) {
        int h = (j * 32 + lane) * 4;
        float4 nsv = ((const float4*)ns)[j * 32 + lane];
        float n0 = xv[j].x * rms * nsv.x;
        float n1 = xv[j].y * rms * nsv.y;
        float n2 = xv[j].z * rms * nsv.z;
        float n3 = xv[j].w * rms * nsv.w;
        __half2 p0 = __floats2half2_rn(n0, n1);
        __half2 p1 = __floats2half2_rn(n2, n3);
        *(uint2*)(g_xn + (size_t)t * Hd + h) =
            make_uint2(*(uint32_t*)&p0, *(uint32_t*)&p1);
        float nv[4] = {n0, n1, n2, n3};
        #pragma unroll
        for (int v = 0; v < 4; v++) {
            const float4* wrow = (const float4*)(wg + (size_t)(h + v) * NE);
            float4 w0 = wrow[0], w1 = wrow[1], w2 = wrow[2], w3 = wrow[3];
            acc[0]  += nv[v] * w0.x;  acc[1]  += nv[v] * w0.y;
            acc[2]  += nv[v] * w0.z;  acc[3]  += nv[v] * w0.w;
            acc[4]  += nv[v] * w1.x;  acc[5]  += nv[v] * w1.y;
            acc[6]  += nv[v] * w1.z;  acc[7]  += nv[v] * w1.w;
            acc[8]  += nv[v] * w2.x;  acc[9]  += nv[v] * w2.y;
            acc[10] += nv[v] * w2.z;  acc[11] += nv[v] * w2.w;
            acc[12] += nv[v] * w3.x;  acc[13] += nv[v] * w3.y;
            acc[14] += nv[v] * w3.z;  acc[15] += nv[v] * w3.w;
        }
    }
    #pragma unroll
    for (int o = 16; o; o >>= 1)
        #pragma unroll
        for (int e = 0; e < NE; e++) acc[e] += __shfl_xor_sync(0xffffffffu, acc[e], o);

    if (lane == 0) {
        float logits[NE];
        #pragma unroll
        for (int e = 0; e < NE; e++) logits[e] = acc[e] + bg[e];
        float vals[TOPK]; int idx[TOPK];
        unsigned used = 0;
        for (int k = 0; k < TOPK; k++) {
            float best = -1e30f; int bi = 0;
            #pragma unroll
            for (int e = 0; e < NE; e++)
                if (!((used >> e) & 1u) && logits[e] > best) { best = logits[e]; bi = e; }
            used |= 1u << bi; vals[k] = best; idx[k] = bi;
        }
        float ex[TOPK], den = 0.f;
        #pragma unroll
        for (int k = 0; k < TOPK; k++) { ex[k] = __expf(vals[k] - vals[0]); den += ex[k]; }
        float inv = 1.f / den;
        #pragma unroll
        for (int k = 0; k < TOPK; k++) {
            int e = idx[k];
            int pos = atomicAdd(&g_cnt[e], 1);
            g_perm[e * T + pos] = t;
            g_gate[e * T + pos] = ex[k] * inv;
        }
    }
}

// ---------------- helpers ----------------
__device__ __forceinline__ void mma16816(float* c, const uint32_t* a, const uint32_t* b) {
    asm volatile(
        "mma.sync.aligned.m16n8k16.row.col.f32.f16.f16.f32 "
        "{%0,%1,%2,%3}, {%4,%5,%6,%7}, {%8,%9}, {%0,%1,%2,%3};\n"
        : "+f"(c[0]), "+f"(c[1]), "+f"(c[2]), "+f"(c[3])
        : "r"(a[0]), "r"(a[1]), "r"(a[2]), "r"(a[3]), "r"(b[0]), "r"(b[1]));
}
__device__ __forceinline__ void cpa16(void* dst, const void* src, int sz) {
    uint32_t d = (uint32_t)__cvta_generic_to_shared(dst);
    asm volatile("cp.async.cg.shared.global [%0], [%1], 16, %2;\n" :: "r"(d), "l"(src), "r"(sz));
}
__device__ __forceinline__ void cpa_commit() { asm volatile("cp.async.commit_group;\n"); }
__device__ __forceinline__ void cpa_wait2()  { asm volatile("cp.async.wait_group 2;\n"); }
__device__ __forceinline__ uint32_t h2pack(float a, float b) {
    __half2 h = __floats2half2_rn(a, b);
    return *(uint32_t*)&h;
}
__device__ __forceinline__ void ldsm4(uint32_t* r, const void* p) {
    uint32_t addr = (uint32_t)__cvta_generic_to_shared(p);
    asm volatile("ldmatrix.sync.aligned.m8n8.x4.shared.b16 {%0,%1,%2,%3}, [%4];"
        : "=r"(r[0]), "=r"(r[1]), "=r"(r[2]), "=r"(r[3]) : "r"(addr));
}
__device__ __forceinline__ void ldsm4t(uint32_t* r, const void* p) {
    uint32_t addr = (uint32_t)__cvta_generic_to_shared(p);
    asm volatile("ldmatrix.sync.aligned.m8n8.x4.trans.shared.b16 {%0,%1,%2,%3}, [%4];"
        : "=r"(r[0]), "=r"(r[1]), "=r"(r[2]), "=r"(r[3]) : "r"(addr));
}

// smem views: As[4][128][40] half, B16[2][32][136] half
struct SmemView {
    __half (*As)[128][40];
    __half (*B16)[32][136];
    int* rowTok;
    float* rowGate;
};
__device__ __forceinline__ SmemView smview(char* base) {
    SmemView s;
    s.As     = (__half(*)[128][40])(base + OFF_A);
    s.B16    = (__half(*)[32][136])(base + OFF_B16);
    s.rowTok = (int*)(base + OFF_TOK);
    s.rowGate= (float*)(base + OFF_GATE);
    return s;
}

// B register-path: thread (ck = tid>>3, l = tid&7) owns row ck, cols {l*4 + j*32}
__device__ __forceinline__ void ldgB(float4* rF, const float* __restrict__ w,
                                     int ld, int k0, int nBase, int tid) {
    int ck = tid >> 3, l = tid & 7;
    const float* row = w + (size_t)(k0 + ck) * ld + nBase + l * 4;
    #pragma unroll
    for (int j = 0; j < 4; j++) rF[j] = *(const float4*)(row + j * 32);
}
__device__ __forceinline__ void stsB(SmemView& sv, int buf, const float4* rF, int tid) {
    int ck = tid >> 3, l = tid & 7;
    #pragma unroll
    for (int j = 0; j < 4; j++) {
        uint2 p = make_uint2(h2pack(rF[j].x, rF[j].y), h2pack(rF[j].z, rF[j].w));
        *(uint2*)&sv.B16[buf][ck][l * 4 + j * 32] = p;
    }
}

// ---------------- kernel 2: grouped GEMM1 + swiglu ----------------
// grid (nTile=16, mTile=4, expert=16), block 256 (8 warps 2x4)
__global__ __launch_bounds__(256, 2) void k_ffn1(
    const float* __restrict__ w1, const float* __restrict__ b1)
{
    extern __shared__ char smbase[];
    SmemView sv = smview(smbase);

    int e = blockIdx.z;
    int cnt = g_cnt[e];
    int mBase = blockIdx.y * 128;
    if (mBase >= cnt) return;
    int nBase = blockIdx.x * 128;
    int validRows = cnt - mBase; if (validRows > 128) validRows = 128;

    int tid = threadIdx.x;
    if (tid < 128) {
        int slot = mBase + tid;
        sv.rowTok[tid] = (slot < cnt) ? g_perm[e * T + slot] : -1;
    }
    __syncthreads();

    int lane = tid & 31, warp = tid >> 5;
    int wm = warp >> 2, wn = warp & 3;
    bool warpLive = (wm * 64) < validRows;

    float acc[4][4][4];
    #pragma unroll
    for (int mf = 0; mf < 4; mf++)
        #pragma unroll
        for (int nf = 0; nf < 4; nf++)
            #pragma unroll
            for (int i = 0; i < 4; i++) acc[mf][nf][i] = 0.f;

    auto issueA = [&](int s) {
        int k0 = s * 32;
        #pragma unroll
        for (int c = 0; c < 2; c++) {
            int ch = tid + c * 256;
            int row = ch >> 2, col = (ch & 3) * 8;
            int tok = sv.rowTok[row];
            if (tok >= 0) cpa16(&sv.As[s & 3][row][col], g_xn + (size_t)tok * Hd + k0 + col, 16);
            else          cpa16(&sv.As[s & 3][row][col], g_xn, 0);
        }
    };

    const int LD = 2 * Id;
    float4 rF[4];

    issueA(0); cpa_commit();
    issueA(1); cpa_commit();
    issueA(2); cpa_commit();
    ldgB(rF, w1 + (size_t)e * Hd * LD, LD, 0, nBase, tid);
    stsB(sv, 0, rF, tid);
    ldgB(rF, w1 + (size_t)e * Hd * LD, LD, 32, nBase, tid);

    const int KT = Hd / 32;
    for (int it = 0; it < KT; it++) {
        cpa_wait2();
        __syncthreads();
        if (it + 1 < KT) stsB(sv, (it + 1) & 1, rF, tid);
        if (warpLive) {
            #pragma unroll
            for (int kk = 0; kk < 32; kk += 16) {
                uint32_t a[4][4], b[4][2];
                #pragma unroll
                for (int mf = 0; mf < 4; mf++) {
                    int r = wm * 64 + mf * 16 + (lane & 15);
                    ldsm4(a[mf], &sv.As[it & 3][r][kk + (lane >> 4) * 8]);
                }
                #pragma unroll
                for (int pair = 0; pair < 2; pair++) {
                    int m = lane >> 3, r = lane & 7;
                    uint32_t rr[4];
                    ldsm4t(rr, &sv.B16[it & 1][kk + (m & 1) * 8 + r][wn * 32 + pair * 16 + (m >> 1) * 8]);
                    b[pair * 2 + 0][0] = rr[0]; b[pair * 2 + 0][1] = rr[1];
                    b[pair * 2 + 1][0] = rr[2]; b[pair * 2 + 1][1] = rr[3];
                }
                #pragma unroll
                for (int mf = 0; mf < 4; mf++)
                    #pragma unroll
                    for (int nf = 0; nf < 4; nf++)
                        mma16816(acc[mf][nf], a[mf], b[nf]);
            }
        }
        if (it + 2 < KT) ldgB(rF, w1 + (size_t)e * Hd * LD, LD, (it + 2) * 32, nBase, tid);
        if (it + 3 < KT) issueA(it + 3);
        cpa_commit();
    }

    // ---- epilogue: swiglu -> smem staging (reuse As area) -> coalesced g_s ----
    __half (*Ss)[72] = (__half(*)[72])(smbase + OFF_A);  // 128 x 72 half = 18432 B
    __syncthreads();                                      // all done reading As/B16
    if (warpLive) {
        int g = lane >> 2, tg = lane & 3;
        #pragma unroll
        for (int mf = 0; mf < 4; mf++) {
            #pragma unroll
            for (int nf = 0; nf < 4; nf++) {
                int ncol = nBase + wn * 32 + nf * 8 + tg * 2;   // even
                float ba = b1[e * (2 * Id) + ncol];
                float bb = b1[e * (2 * Id) + ncol + 1];
                int sl = wn * 16 + nf * 4 + tg;                 // local scol 0..63
                #pragma unroll
                for (int h = 0; h < 2; h++) {
                    int row = wm * 64 + mf * 16 + g + h * 8;
                    float av = acc[mf][nf][h * 2 + 0] + ba;
                    float bv = acc[mf][nf][h * 2 + 1] + bb;
                    av = fminf(av, 7.0f);
                    bv = fminf(fmaxf(bv, -7.0f), 7.0f);
                    float sig = __frcp_rn(1.f + __expf(-1.702f * av));
                    Ss[row][sl] = __float2half(av * sig * (bv + 1.f));
                }
            }
        }
    }
    __syncthreads();
    {
        int r0 = tid >> 3, cl = (tid & 7) * 8;
        #pragma unroll
        for (int p = 0; p < 4; p++) {
            int row = p * 32 + r0;
            int slot = mBase + row;
            if (slot < cnt) {
                uint4 v = *(uint4*)&Ss[row][cl];
                *(uint4*)(g_s + ((size_t)(e * T + slot)) * Id + (nBase >> 1) + cl) = v;
            }
        }
    }
}

// ---------------- kernel 3: grouped GEMM2 + gated scatter ----------------
// grid (nTile=8, mTile=4, expert=16), block 256
__global__ __launch_bounds__(256, 2) void k_ffn2(
    const float* __restrict__ w2, const float* __restrict__ b2, float* __restrict__ out)
{
    extern __shared__ char smbase[];
    SmemView sv = smview(smbase);

    int e = blockIdx.z;
    int cnt = g_cnt[e];
    int mBase = blockIdx.y * 128;
    if (mBase >= cnt) return;
    int nBase = blockIdx.x * 128;
    int validRows = cnt - mBase; if (validRows > 128) validRows = 128;

    int tid = threadIdx.x;
    if (tid < 128) {
        int slot = mBase + tid;
        if (slot < cnt) { sv.rowTok[tid] = g_perm[e * T + slot]; sv.rowGate[tid] = g_gate[e * T + slot]; }
        else            { sv.rowTok[tid] = -1;                   sv.rowGate[tid] = 0.f; }
    }
    __syncthreads();

    int lane = tid & 31, warp = tid >> 5;
    int wm = warp >> 2, wn = warp & 3;
    bool warpLive = (wm * 64) < validRows;

    float acc[4][4][4];
    #pragma unroll
    for (int mf = 0; mf < 4; mf++)
        #pragma unroll
        for (int nf = 0; nf < 4; nf++)
            #pragma unroll
            for (int i = 0; i < 4; i++) acc[mf][nf][i] = 0.f;

    auto issueA = [&](int s) {
        int k0 = s * 32;
        #pragma unroll
        for (int c = 0; c < 2; c++) {
            int ch = tid + c * 256;
            int row = ch >> 2, col = (ch & 3) * 8;
            int valid = (row < validRows) ? 16 : 0;
            const __half* src = g_s + ((size_t)(e * T + mBase + row)) * Id + k0 + col;
            cpa16(&sv.As[s & 3][row][col], src, valid);
        }
    };

    float4 rF[4];

    issueA(0); cpa_commit();
    issueA(1); cpa_commit();
    issueA(2); cpa_commit();
    ldgB(rF, w2 + (size_t)e * Id * Hd, Hd, 0, nBase, tid);
    stsB(sv, 0, rF, tid);
    ldgB(rF, w2 + (size_t)e * Id * Hd, Hd, 32, nBase, tid);

    const int KT = Id / 32;
    for (int it = 0; it < KT; it++) {
        cpa_wait2();
        __syncthreads();
        if (it + 1 < KT) stsB(sv, (it + 1) & 1, rF, tid);
        if (warpLive) {
            #pragma unroll
            for (int kk = 0; kk < 32; kk += 16) {
                uint32_t a[4][4], b[4][2];
                #pragma unroll
                for (int mf = 0; mf < 4; mf++) {
                    int r = wm * 64 + mf * 16 + (lane & 15);
                    ldsm4(a[mf], &sv.As[it & 3][r][kk + (lane >> 4) * 8]);
                }
                #pragma unroll
                for (int pair = 0; pair < 2; pair++) {
                    int m = lane >> 3, r = lane & 7;
                    uint32_t rr[4];
                    ldsm4t(rr, &sv.B16[it & 1][kk + (m & 1) * 8 + r][wn * 32 + pair * 16 + (m >> 1) * 8]);
                    b[pair * 2 + 0][0] = rr[0]; b[pair * 2 + 0][1] = rr[1];
                    b[pair * 2 + 1][0] = rr[2]; b[pair * 2 + 1][1] = rr[3];
                }
                #pragma unroll
                for (int mf = 0; mf < 4; mf++)
                    #pragma unroll
                    for (int nf = 0; nf < 4; nf++)
                        mma16816(acc[mf][nf], a[mf], b[nf]);
            }
        }
        if (it + 2 < KT) ldgB(rF, w2 + (size_t)e * Id * Hd, Hd, (it + 2) * 32, nBase, tid);
        if (it + 3 < KT) issueA(it + 3);
        cpa_commit();
    }

    if (warpLive) {
        int g = lane >> 2, tg = lane & 3;
        #pragma unroll
        for (int mf = 0; mf < 4; mf++) {
            #pragma unroll
            for (int nf = 0; nf < 4; nf++) {
                int ncol = nBase + wn * 32 + nf * 8 + tg * 2;
                float b2a = b2[e * Hd + ncol];
                float b2b = b2[e * Hd + ncol + 1];
                #pragma unroll
                for (int h = 0; h < 2; h++) {
                    int row = wm * 64 + mf * 16 + g + h * 8;
                    int slot = mBase + row;
                    if (slot < cnt) {
                        int tok = sv.rowTok[row];
                        float gt = sv.rowGate[row];
                        atomicAdd(&out[(size_t)tok * Hd + ncol],     gt * (acc[mf][nf][h * 2 + 0] + b2a));
                        atomicAdd(&out[(size_t)tok * Hd + ncol + 1], gt * (acc[mf][nf][h * 2 + 1] + b2b));
                    }
                }
            }
        }
    }
}

// ---------------- launch ----------------
extern "C" void kernel_launch(void* const* d_in, const int* in_sizes, int n_in,
                              void* d_out, int out_size)
{
    const float* x  = (const float*)d_in[0];
    const float* ns = (const float*)d_in[1];
    const float* wg = (const float*)d_in[2];
    const float* bg = (const float*)d_in[3];
    const float* w1 = (const float*)d_in[4];
    const float* b1 = (const float*)d_in[5];
    const float* w2 = (const float*)d_in[6];
    const float* b2 = (const float*)d_in[7];
    float* out = (float*)d_out;

    cudaFuncSetAttribute(k_ffn1, cudaFuncAttributeMaxDynamicSharedMemorySize, DYN_SMEM);
    cudaFuncSetAttribute(k_ffn2, cudaFuncAttributeMaxDynamicSharedMemorySize, DYN_SMEM);

    k_zero<<<1, 32>>>();
    k_norm_route<<<128, 256>>>(x, ns, wg, bg, out);
    k_ffn1<<<dim3(16, 4, 16), 256, DYN_SMEM>>>(w1, b1);
    k_ffn2<<<dim3(8, 4, 16), 256, DYN_SMEM>>>(w2, b2, out);
}